// round 2
// baseline (speedup 1.0000x reference)
#include <cuda_runtime.h>
#include <math.h>

#define NLAYER 2
#define BATCH  2
#define SEQ    2048
#define HID    1024
#define NHEAD  16
#define DHEAD  64
#define FFDIM  4096
#define NTOK   (BATCH*SEQ)      // 4096
#define QKVDIM (3*HID)          // 3072

// ---------------- scratch (device globals: no allocation allowed) ----------------
__device__ float g_h[NTOK*HID];                                  // 16 MB  LN output
__device__ float g_qkv[(size_t)NTOK*QKVDIM];                     // 48 MB
__device__ float g_scores[(size_t)BATCH*NHEAD*SEQ*SEQ];          // 512 MB
__device__ float g_ctx[NTOK*HID];                                // 16 MB
__device__ float g_ff[(size_t)NTOK*FFDIM];                       // 64 MB

// ---------------- reductions ----------------
__device__ __forceinline__ float warpSum(float v) {
#pragma unroll
    for (int o = 16; o > 0; o >>= 1) v += __shfl_xor_sync(0xffffffffu, v, o);
    return v;
}
__device__ __forceinline__ float warpMax(float v) {
#pragma unroll
    for (int o = 16; o > 0; o >>= 1) v = fmaxf(v, __shfl_xor_sync(0xffffffffu, v, o));
    return v;
}

// ---------------- LayerNorm: one block per token, H=1024, 256 threads ----------------
__global__ __launch_bounds__(256)
void ln_kernel(const float* __restrict__ x, const float* __restrict__ w,
               const float* __restrict__ b, float* __restrict__ out)
{
    __shared__ float sh[8];
    __shared__ float stat;
    const int t = blockIdx.x;
    const float* xr = x + (size_t)t * HID;
    const int lane = threadIdx.x & 31, wp = threadIdx.x >> 5;

    float v[4];
    float s = 0.f;
#pragma unroll
    for (int i = 0; i < 4; i++) { v[i] = xr[threadIdx.x + i * 256]; s += v[i]; }
    s = warpSum(s);
    if (lane == 0) sh[wp] = s;
    __syncthreads();
    if (threadIdx.x == 0) {
        float r = 0.f;
#pragma unroll
        for (int i = 0; i < 8; i++) r += sh[i];
        stat = r * (1.0f / HID);
    }
    __syncthreads();
    const float mu = stat;

    float s2 = 0.f;
#pragma unroll
    for (int i = 0; i < 4; i++) { float d = v[i] - mu; s2 += d * d; }
    s2 = warpSum(s2);
    __syncthreads();                    // protect sh reuse
    if (lane == 0) sh[wp] = s2;
    __syncthreads();
    if (threadIdx.x == 0) {
        float r = 0.f;
#pragma unroll
        for (int i = 0; i < 8; i++) r += sh[i];
        stat = rsqrtf(r * (1.0f / HID) + 1e-5f);
    }
    __syncthreads();
    const float rs = stat;

    float* orow = out + (size_t)t * HID;
#pragma unroll
    for (int i = 0; i < 4; i++) {
        int c = threadIdx.x + i * 256;
        orow[c] = (v[i] - mu) * rs * w[c] + b[c];
    }
}

// ---------------- row softmax over S=2048, one block per row ----------------
__global__ __launch_bounds__(256)
void softmax_kernel(float* __restrict__ scores)
{
    __shared__ float sh[8];
    __shared__ float stat;
    float* p = scores + (size_t)blockIdx.x * SEQ;
    const int lane = threadIdx.x & 31, wp = threadIdx.x >> 5;

    float v[8];
    float m = -1e30f;
#pragma unroll
    for (int i = 0; i < 8; i++) { v[i] = p[threadIdx.x + i * 256]; m = fmaxf(m, v[i]); }
    m = warpMax(m);
    if (lane == 0) sh[wp] = m;
    __syncthreads();
    if (threadIdx.x == 0) {
        float r = sh[0];
#pragma unroll
        for (int i = 1; i < 8; i++) r = fmaxf(r, sh[i]);
        stat = r;
    }
    __syncthreads();
    const float mx = stat;

    float s = 0.f;
#pragma unroll
    for (int i = 0; i < 8; i++) { v[i] = expf(v[i] - mx); s += v[i]; }
    s = warpSum(s);
    __syncthreads();
    if (lane == 0) sh[wp] = s;
    __syncthreads();
    if (threadIdx.x == 0) {
        float r = 0.f;
#pragma unroll
        for (int i = 0; i < 8; i++) r += sh[i];
        stat = 1.0f / r;
    }
    __syncthreads();
    const float inv = stat;
#pragma unroll
    for (int i = 0; i < 8; i++) p[threadIdx.x + i * 256] = v[i] * inv;
}

// ---------------- generic NT SGEMM: C[M,N] = A[M,K] * B[N,K]^T + bias (+epilogue) ----
// EPI: 0 = bias, 1 = bias+gelu(exact), 2 = bias+residual
// 128x128x16 tiles, 256 threads, 8x8 microtiles. M,N % 128 == 0, K % 16 == 0.
template<int EPI>
__global__ __launch_bounds__(256)
void gemm_nt(const float* __restrict__ A, int lda,
             const float* __restrict__ B, int ldb,
             const float* __restrict__ bias,
             const float* __restrict__ res,
             float* __restrict__ C, int ldc, int K)
{
    __shared__ float As[16][128];
    __shared__ float Bs[16][128];
    const int tid = threadIdx.x;
    const int rowBlock = blockIdx.y * 128;
    const int colBlock = blockIdx.x * 128;
    const int lr = tid >> 2;
    const int lc = (tid & 3) << 2;

    float acc[8][8];
#pragma unroll
    for (int i = 0; i < 8; i++)
#pragma unroll
        for (int j = 0; j < 8; j++) acc[i][j] = 0.f;

    const float* Ap = A + (size_t)(rowBlock + lr) * lda + lc;
    const float* Bp = B + (size_t)(colBlock + lr) * ldb + lc;

    for (int kt = 0; kt < K; kt += 16) {
#pragma unroll
        for (int hf = 0; hf < 2; hf++) {
            const int r = lr + hf * 64;
            float4 va = *(const float4*)(Ap + (size_t)hf * 64 * lda + kt);
            float4 vb = *(const float4*)(Bp + (size_t)hf * 64 * ldb + kt);
            As[lc + 0][r] = va.x; As[lc + 1][r] = va.y; As[lc + 2][r] = va.z; As[lc + 3][r] = va.w;
            Bs[lc + 0][r] = vb.x; Bs[lc + 1][r] = vb.y; Bs[lc + 2][r] = vb.z; Bs[lc + 3][r] = vb.w;
        }
        __syncthreads();
        const int tr = (tid >> 4) << 3;
        const int tc = (tid & 15) << 3;
#pragma unroll
        for (int k = 0; k < 16; k++) {
            float ra[8], rb[8];
            *(float4*)&ra[0] = *(const float4*)&As[k][tr];
            *(float4*)&ra[4] = *(const float4*)&As[k][tr + 4];
            *(float4*)&rb[0] = *(const float4*)&Bs[k][tc];
            *(float4*)&rb[4] = *(const float4*)&Bs[k][tc + 4];
#pragma unroll
            for (int i = 0; i < 8; i++)
#pragma unroll
                for (int j = 0; j < 8; j++)
                    acc[i][j] = fmaf(ra[i], rb[j], acc[i][j]);
        }
        __syncthreads();
    }

    const int tr = rowBlock + ((tid >> 4) << 3);
    const int tc = colBlock + ((tid & 15) << 3);
#pragma unroll
    for (int i = 0; i < 8; i++) {
#pragma unroll
        for (int j = 0; j < 8; j++) {
            float v = acc[i][j] + bias[tc + j];
            if (EPI == 1) v = 0.5f * v * (1.0f + erff(v * 0.70710678118654752440f));
            if (EPI == 2) v += res[(size_t)(tr + i) * ldc + (tc + j)];
            C[(size_t)(tr + i) * ldc + (tc + j)] = v;
        }
    }
}

// ---------------- attention scores: S = Q K^T / 8 + alibi, causal mask ----------------
// grid (SEQ/128, SEQ/128, B*NH). K dim = 64.
__global__ __launch_bounds__(256)
void scores_kernel(const float* __restrict__ qkv, const float* __restrict__ alibi,
                   float* __restrict__ scores)
{
    __shared__ float As[16][128];
    __shared__ float Bs[16][128];
    const int z = blockIdx.z;
    const int b = z >> 4;
    const int hh = z & 15;
    const int rowBlock = blockIdx.y * 128;
    const int colBlock = blockIdx.x * 128;
    float* C = scores + (size_t)z * SEQ * SEQ;
    const int tid = threadIdx.x;

    // fully-masked tile: col > row everywhere
    if (colBlock > rowBlock + 127) {
        const int tr = rowBlock + ((tid >> 4) << 3);
        const int tc = colBlock + ((tid & 15) << 3);
#pragma unroll
        for (int i = 0; i < 8; i++)
#pragma unroll
            for (int j = 0; j < 8; j++)
                C[(size_t)(tr + i) * SEQ + (tc + j)] = -10000.0f;
        return;
    }

    const float* Q  = qkv + (size_t)b * SEQ * QKVDIM + hh * DHEAD;
    const float* Kp = Q + HID;
    const float* al = alibi + (size_t)z * SEQ;
    const int lr = tid >> 2;
    const int lc = (tid & 3) << 2;

    float acc[8][8];
#pragma unroll
    for (int i = 0; i < 8; i++)
#pragma unroll
        for (int j = 0; j < 8; j++) acc[i][j] = 0.f;

#pragma unroll
    for (int kt = 0; kt < DHEAD; kt += 16) {
#pragma unroll
        for (int hf = 0; hf < 2; hf++) {
            const int r = lr + hf * 64;
            float4 va = *(const float4*)&Q [(size_t)(rowBlock + r) * QKVDIM + kt + lc];
            float4 vb = *(const float4*)&Kp[(size_t)(colBlock + r) * QKVDIM + kt + lc];
            As[lc + 0][r] = va.x; As[lc + 1][r] = va.y; As[lc + 2][r] = va.z; As[lc + 3][r] = va.w;
            Bs[lc + 0][r] = vb.x; Bs[lc + 1][r] = vb.y; Bs[lc + 2][r] = vb.z; Bs[lc + 3][r] = vb.w;
        }
        __syncthreads();
        const int tr = (tid >> 4) << 3;
        const int tc = (tid & 15) << 3;
#pragma unroll
        for (int k = 0; k < 16; k++) {
            float ra[8], rb[8];
            *(float4*)&ra[0] = *(const float4*)&As[k][tr];
            *(float4*)&ra[4] = *(const float4*)&As[k][tr + 4];
            *(float4*)&rb[0] = *(const float4*)&Bs[k][tc];
            *(float4*)&rb[4] = *(const float4*)&Bs[k][tc + 4];
#pragma unroll
            for (int i = 0; i < 8; i++)
#pragma unroll
                for (int j = 0; j < 8; j++)
                    acc[i][j] = fmaf(ra[i], rb[j], acc[i][j]);
        }
        __syncthreads();
    }

    const int tr = rowBlock + ((tid >> 4) << 3);
    const int tc = colBlock + ((tid & 15) << 3);
#pragma unroll
    for (int i = 0; i < 8; i++) {
#pragma unroll
        for (int j = 0; j < 8; j++) {
            const int r = tr + i, c = tc + j;
            float v = acc[i][j] * 0.125f + al[c];
            if (c > r) v = -10000.0f;
            C[(size_t)r * SEQ + c] = v;
        }
    }
}

// ---------------- PV: ctx[q,d] = sum_k P[q,k] V[k,d]  (NN, N=64) --------------------
// grid (SEQ/128, 1, B*NH). 128x64 tile, BK=16, 8x4 microtiles.
__global__ __launch_bounds__(256)
void pv_kernel(const float* __restrict__ scores, const float* __restrict__ qkv,
               float* __restrict__ ctx)
{
    __shared__ float As[16][128];
    __shared__ float Bs[16][64];
    const int z = blockIdx.z;
    const int b = z >> 4;
    const int hh = z & 15;
    const float* P = scores + (size_t)z * SEQ * SEQ;
    const float* V = qkv + (size_t)b * SEQ * QKVDIM + 2 * HID + hh * DHEAD;
    float* C = ctx + (size_t)b * SEQ * HID + hh * DHEAD;
    const int tid = threadIdx.x;
    const int rowBlock = blockIdx.x * 128;
    const int lr = tid >> 2, lc = (tid & 3) << 2;
    const int bk = tid >> 4, bn = (tid & 15) << 2;

    float acc[8][4];
#pragma unroll
    for (int i = 0; i < 8; i++)
#pragma unroll
        for (int j = 0; j < 4; j++) acc[i][j] = 0.f;

    for (int kt = 0; kt < SEQ; kt += 16) {
#pragma unroll
        for (int hf = 0; hf < 2; hf++) {
            const int r = lr + hf * 64;
            float4 va = *(const float4*)&P[(size_t)(rowBlock + r) * SEQ + kt + lc];
            As[lc + 0][r] = va.x; As[lc + 1][r] = va.y; As[lc + 2][r] = va.z; As[lc + 3][r] = va.w;
        }
        float4 vb = *(const float4*)&V[(size_t)(kt + bk) * QKVDIM + bn];
        *(float4*)&Bs[bk][bn] = vb;
        __syncthreads();
        const int tr = (tid >> 4) << 3;
        const int tc = (tid & 15) << 2;
#pragma unroll
        for (int k = 0; k < 16; k++) {
            float ra[8], rb[4];
            *(float4*)&ra[0] = *(const float4*)&As[k][tr];
            *(float4*)&ra[4] = *(const float4*)&As[k][tr + 4];
            *(float4*)&rb[0] = *(const float4*)&Bs[k][tc];
#pragma unroll
            for (int i = 0; i < 8; i++)
#pragma unroll
                for (int j = 0; j < 4; j++)
                    acc[i][j] = fmaf(ra[i], rb[j], acc[i][j]);
        }
        __syncthreads();
    }

    const int tr = rowBlock + ((tid >> 4) << 3);
    const int tc = (tid & 15) << 2;
#pragma unroll
    for (int i = 0; i < 8; i++)
#pragma unroll
        for (int j = 0; j < 4; j++)
            C[(size_t)(tr + i) * HID + tc + j] = acc[i][j];
}

// ---------------- launch ----------------
extern "C" void kernel_launch(void* const* d_in, const int* in_sizes, int n_in,
                              void* d_out, int out_size)
{
    (void)in_sizes; (void)n_in; (void)out_size;
    const float* hidden  = (const float*)d_in[0];
    const float* alibi   = (const float*)d_in[1];
    const float* qkv_w   = (const float*)d_in[2];
    const float* qkv_b   = (const float*)d_in[3];
    const float* dense_w = (const float*)d_in[4];
    const float* dense_b = (const float*)d_in[5];
    const float* w1      = (const float*)d_in[6];
    const float* b1      = (const float*)d_in[7];
    const float* w2      = (const float*)d_in[8];
    const float* b2      = (const float*)d_in[9];
    const float* ln1w    = (const float*)d_in[10];
    const float* ln1b    = (const float*)d_in[11];
    const float* ln2w    = (const float*)d_in[12];
    const float* ln2b    = (const float*)d_in[13];
    float* x = (float*)d_out;

    float *ph, *pqkv, *pscores, *pctx, *pff;
    cudaGetSymbolAddress((void**)&ph,      g_h);
    cudaGetSymbolAddress((void**)&pqkv,    g_qkv);
    cudaGetSymbolAddress((void**)&pscores, g_scores);
    cudaGetSymbolAddress((void**)&pctx,    g_ctx);
    cudaGetSymbolAddress((void**)&pff,     g_ff);

    cudaMemcpyAsync(x, hidden, sizeof(float) * (size_t)NTOK * HID,
                    cudaMemcpyDeviceToDevice);

    for (int l = 0; l < NLAYER; l++) {
        // --- attention ---
        ln_kernel<<<NTOK, 256>>>(x, ln1w + l * HID, ln1b + l * HID, ph);
        gemm_nt<0><<<dim3(QKVDIM / 128, NTOK / 128), 256>>>(
            ph, HID, qkv_w + (size_t)l * QKVDIM * HID, HID,
            qkv_b + (size_t)l * QKVDIM, nullptr, pqkv, QKVDIM, HID);
        scores_kernel<<<dim3(SEQ / 128, SEQ / 128, BATCH * NHEAD), 256>>>(
            pqkv, alibi, pscores);
        softmax_kernel<<<BATCH * NHEAD * SEQ, 256>>>(pscores);
        pv_kernel<<<dim3(SEQ / 128, 1, BATCH * NHEAD), 256>>>(pscores, pqkv, pctx);
        gemm_nt<2><<<dim3(HID / 128, NTOK / 128), 256>>>(
            pctx, HID, dense_w + (size_t)l * HID * HID, HID,
            dense_b + (size_t)l * HID, x, x, HID, HID);
        // --- MLP ---
        ln_kernel<<<NTOK, 256>>>(x, ln2w + l * HID, ln2b + l * HID, ph);
        gemm_nt<1><<<dim3(FFDIM / 128, NTOK / 128), 256>>>(
            ph, HID, w1 + (size_t)l * FFDIM * HID, HID,
            b1 + (size_t)l * FFDIM, nullptr, pff, FFDIM, HID);
        gemm_nt<2><<<dim3(HID / 128, NTOK / 128), 256>>>(
            pff, FFDIM, w2 + (size_t)l * HID * FFDIM, FFDIM,
            b2 + (size_t)l * HID, x, x, HID, FFDIM);
    }
}

// round 4
// speedup vs baseline: 5.6519x; 5.6519x over previous
#include <cuda_runtime.h>
#include <cuda_bf16.h>
#include <math.h>
#include <stdint.h>

#define NLAYER 2
#define BATCH  2
#define SEQ    2048
#define HID    1024
#define NHEAD  16
#define DHEAD  64
#define FFDIM  4096
#define NTOK   (BATCH*SEQ)      // 4096
#define QKVDIM (3*HID)          // 3072
#define KPAD   40               // 32-elem K chunk padded to 40 (80B rows, conflict-free)

// ---------------- scratch (device globals) ----------------
__device__ __nv_bfloat16 g_h[NTOK*HID];
__device__ __nv_bfloat16 g_qkv[(size_t)NTOK*QKVDIM];
__device__ float         g_scores[(size_t)BATCH*NHEAD*SEQ*SEQ];
__device__ __nv_bfloat16 g_probs[(size_t)BATCH*NHEAD*SEQ*SEQ];
__device__ __nv_bfloat16 g_vt[(size_t)BATCH*NHEAD*DHEAD*SEQ];
__device__ __nv_bfloat16 g_ctx[NTOK*HID];
__device__ __nv_bfloat16 g_ff[(size_t)NTOK*FFDIM];
__device__ __nv_bfloat16 g_wq[(size_t)NLAYER*QKVDIM*HID];
__device__ __nv_bfloat16 g_wd[(size_t)NLAYER*HID*HID];
__device__ __nv_bfloat16 g_w1[(size_t)NLAYER*FFDIM*HID];
__device__ __nv_bfloat16 g_w2[(size_t)NLAYER*HID*FFDIM];

// ---------------- helpers ----------------
__device__ __forceinline__ uint32_t smem_u32(const void* p) {
    uint32_t a;
    asm("{ .reg .u64 t; cvta.to.shared.u64 t, %1; cvt.u32.u64 %0, t; }" : "=r"(a) : "l"(p));
    return a;
}
__device__ __forceinline__ void cp16(uint32_t s, const void* g) {
    asm volatile("cp.async.cg.shared.global [%0], [%1], 16;" :: "r"(s), "l"(g));
}
#define CP_COMMIT asm volatile("cp.async.commit_group;")
#define CP_WAIT1  asm volatile("cp.async.wait_group 1;")
#define CP_WAIT0  asm volatile("cp.async.wait_group 0;")

__device__ __forceinline__ void ldmx4(uint32_t* r, uint32_t addr) {
    asm volatile("ldmatrix.sync.aligned.m8n8.x4.shared.b16 {%0,%1,%2,%3}, [%4];"
                 : "=r"(r[0]), "=r"(r[1]), "=r"(r[2]), "=r"(r[3]) : "r"(addr));
}
__device__ __forceinline__ void mma16816(float* c, const uint32_t* a, const uint32_t* b) {
    asm volatile("mma.sync.aligned.m16n8k16.row.col.f32.bf16.bf16.f32 "
                 "{%0,%1,%2,%3}, {%4,%5,%6,%7}, {%8,%9}, {%0,%1,%2,%3};"
                 : "+f"(c[0]), "+f"(c[1]), "+f"(c[2]), "+f"(c[3])
                 : "r"(a[0]), "r"(a[1]), "r"(a[2]), "r"(a[3]), "r"(b[0]), "r"(b[1]));
}
__device__ __forceinline__ uint32_t pack_bf2(float a, float b) {
    __nv_bfloat162 h = __floats2bfloat162_rn(a, b);
    return *(uint32_t*)&h;
}
__device__ __forceinline__ float gelu_f(float v) {
    return 0.5f * v * (1.0f + erff(v * 0.70710678118654752440f));
}
__device__ __forceinline__ float warpSum(float v) {
#pragma unroll
    for (int o = 16; o > 0; o >>= 1) v += __shfl_xor_sync(0xffffffffu, v, o);
    return v;
}
__device__ __forceinline__ float warpMax(float v) {
#pragma unroll
    for (int o = 16; o > 0; o >>= 1) v = fmaxf(v, __shfl_xor_sync(0xffffffffu, v, o));
    return v;
}

// load ROWS x 32 bf16 chunk from g (row stride ld elems) into smem (KPAD-elem rows)
template<int ROWS>
__device__ __forceinline__ void cp_chunk(uint32_t sbase, const __nv_bfloat16* g, int ld, int tid) {
#pragma unroll
    for (int it = 0; it < ROWS / 64; it++) {
        int idx = tid + it * 256;
        int row = idx >> 2, q = idx & 3;
        cp16(sbase + (uint32_t)(row * KPAD + q * 8) * 2, g + (size_t)row * ld + q * 8);
    }
}

// one 32-wide K-chunk of warp-level MMAs. NT = n8 tiles per warp (warp n-width = NT*8)
template<int NT>
__device__ __forceinline__ void mma_chunk(float (&acc)[2][NT][4], uint32_t abase, uint32_t bbase,
                                          int wm, int wn, int lane) {
#pragma unroll
    for (int ks = 0; ks < 32; ks += 16) {
        uint32_t a[2][4];
#pragma unroll
        for (int mt = 0; mt < 2; mt++) {
            int row = wm * 32 + mt * 16 + (lane & 7) + ((lane >> 3) & 1) * 8;
            int col = ks + ((lane >> 4) & 1) * 8;
            ldmx4(a[mt], abase + (uint32_t)(row * KPAD + col) * 2);
        }
        uint32_t bf[NT][2];
#pragma unroll
        for (int nb = 0; nb < NT / 2; nb++) {
            int row = wn * (NT * 8) + nb * 16 + (lane & 7) + ((lane >> 4) & 1) * 8;
            int col = ks + ((lane >> 3) & 1) * 8;
            uint32_t r[4];
            ldmx4(r, bbase + (uint32_t)(row * KPAD + col) * 2);
            bf[2 * nb][0] = r[0]; bf[2 * nb][1] = r[1];
            bf[2 * nb + 1][0] = r[2]; bf[2 * nb + 1][1] = r[3];
        }
#pragma unroll
        for (int mt = 0; mt < 2; mt++)
#pragma unroll
            for (int nt = 0; nt < NT; nt++)
                mma16816(acc[mt][nt], a[mt], bf[nt]);
    }
}

// ---------------- LayerNorm (fp32 in, bf16 out) ----------------
__global__ __launch_bounds__(256)
void ln_kernel(const float* __restrict__ x, const float* __restrict__ w,
               const float* __restrict__ b, __nv_bfloat16* __restrict__ out)
{
    __shared__ float sh[8];
    __shared__ float stat;
    const int t = blockIdx.x;
    const float* xr = x + (size_t)t * HID;
    const int lane = threadIdx.x & 31, wp = threadIdx.x >> 5;

    float v[4];
    float s = 0.f;
#pragma unroll
    for (int i = 0; i < 4; i++) { v[i] = xr[threadIdx.x + i * 256]; s += v[i]; }
    s = warpSum(s);
    if (lane == 0) sh[wp] = s;
    __syncthreads();
    if (threadIdx.x == 0) {
        float r = 0.f;
#pragma unroll
        for (int i = 0; i < 8; i++) r += sh[i];
        stat = r * (1.0f / HID);
    }
    __syncthreads();
    const float mu = stat;

    float s2 = 0.f;
#pragma unroll
    for (int i = 0; i < 4; i++) { float d = v[i] - mu; s2 += d * d; }
    s2 = warpSum(s2);
    __syncthreads();
    if (lane == 0) sh[wp] = s2;
    __syncthreads();
    if (threadIdx.x == 0) {
        float r = 0.f;
#pragma unroll
        for (int i = 0; i < 8; i++) r += sh[i];
        stat = rsqrtf(r * (1.0f / HID) + 1e-5f);
    }
    __syncthreads();
    const float rs = stat;

    __nv_bfloat16* orow = out + (size_t)t * HID;
#pragma unroll
    for (int i = 0; i < 4; i++) {
        int c = threadIdx.x + i * 256;
        orow[c] = __float2bfloat16((v[i] - mu) * rs * w[c] + b[c]);
    }
}

// ---------------- weight convert fp32 -> bf16 ----------------
__global__ __launch_bounds__(256)
void cvt_kernel(const float* __restrict__ src, __nv_bfloat16* __restrict__ dst, int n4)
{
    int i = blockIdx.x * 256 + threadIdx.x;
    if (i < n4) {
        float4 v = ((const float4*)src)[i];
        uint2 o;
        o.x = pack_bf2(v.x, v.y);
        o.y = pack_bf2(v.z, v.w);
        ((uint2*)dst)[i] = o;
    }
}

// ---------------- V transpose: qkv v-part -> [B,NH,DH,S] ----------------
__global__ void vtrans_kernel(const __nv_bfloat16* __restrict__ qkv, __nv_bfloat16* __restrict__ vt)
{
    __shared__ __nv_bfloat16 t[32][33];
    const int z = blockIdx.z, b = z >> 4, h = z & 15;
    const int s0 = blockIdx.x * 32, d0 = blockIdx.y * 32;
    const int tx = threadIdx.x, ty = threadIdx.y;
    t[ty][tx] = qkv[(size_t)(b * SEQ + s0 + ty) * QKVDIM + 2 * HID + h * DHEAD + d0 + tx];
    __syncthreads();
    vt[(size_t)z * DHEAD * SEQ + (size_t)(d0 + ty) * SEQ + s0 + tx] = t[tx][ty];
}

// ---------------- softmax: fp32 scores -> bf16 probs, causal-truncated ----------------
__global__ __launch_bounds__(256)
void softmax_kernel(const float* __restrict__ scores, __nv_bfloat16* __restrict__ probs)
{
    __shared__ float sh[8];
    __shared__ float stat;
    const int row = blockIdx.x;              // z*SEQ + q
    const int q = row & (SEQ - 1);
    const int n4 = (((q >> 7) + 1) << 7) >> 2;   // float4 count: 32..512
    const float4* p = (const float4*)(scores + (size_t)row * SEQ);
    const int lane = threadIdx.x & 31, wp = threadIdx.x >> 5;

    float4 v[2];
    float m = -1e30f;
#pragma unroll
    for (int i = 0; i < 2; i++) {
        int idx = threadIdx.x + i * 256;
        if (idx < n4) {
            v[i] = p[idx];
            m = fmaxf(m, fmaxf(fmaxf(v[i].x, v[i].y), fmaxf(v[i].z, v[i].w)));
        }
    }
    m = warpMax(m);
    if (lane == 0) sh[wp] = m;
    __syncthreads();
    if (threadIdx.x == 0) {
        float r = sh[0];
#pragma unroll
        for (int i = 1; i < 8; i++) r = fmaxf(r, sh[i]);
        stat = r;
    }
    __syncthreads();
    const float mx = stat;

    float s = 0.f;
#pragma unroll
    for (int i = 0; i < 2; i++) {
        int idx = threadIdx.x + i * 256;
        if (idx < n4) {
            v[i].x = __expf(v[i].x - mx); v[i].y = __expf(v[i].y - mx);
            v[i].z = __expf(v[i].z - mx); v[i].w = __expf(v[i].w - mx);
            s += v[i].x + v[i].y + v[i].z + v[i].w;
        }
    }
    s = warpSum(s);
    __syncthreads();
    if (lane == 0) sh[wp] = s;
    __syncthreads();
    if (threadIdx.x == 0) {
        float r = 0.f;
#pragma unroll
        for (int i = 0; i < 8; i++) r += sh[i];
        stat = 1.0f / r;
    }
    __syncthreads();
    const float inv = stat;

    uint2* o = (uint2*)(probs + (size_t)row * SEQ);
#pragma unroll
    for (int i = 0; i < 2; i++) {
        int idx = threadIdx.x + i * 256;
        if (idx < n4) {
            uint2 w2;
            w2.x = pack_bf2(v[i].x * inv, v[i].y * inv);
            w2.y = pack_bf2(v[i].z * inv, v[i].w * inv);
            o[idx] = w2;
        }
    }
}

// ---------------- bf16 tensor-core NT GEMM: C[M,N] = A[M,K] B[N,K]^T + epi ----------
// EPI: 0 = bias -> bf16, 1 = bias+gelu -> bf16, 2 = bias+residual -> fp32
__global__ __launch_bounds__(256, 2)
void mm_gemm_epi0(const __nv_bfloat16*, int, const __nv_bfloat16*, int,
                  const float*, const float*, void*, int, int);

template<int EPI>
__global__ __launch_bounds__(256, 2)
void mm_gemm(const __nv_bfloat16* __restrict__ A, int lda,
             const __nv_bfloat16* __restrict__ B, int ldb,
             const float* __restrict__ bias, const float* __restrict__ res,
             void* __restrict__ Cout, int ldc, int K)
{
    __shared__ __nv_bfloat16 As[2][128 * KPAD];
    __shared__ __nv_bfloat16 Bs[2][128 * KPAD];
    const int tid = threadIdx.x, wid = tid >> 5, lane = tid & 31;
    const int wm = wid & 3, wn = wid >> 2;
    const int rowB = blockIdx.y * 128, colB = blockIdx.x * 128;
    const uint32_t as[2] = { smem_u32(As[0]), smem_u32(As[1]) };
    const uint32_t bs[2] = { smem_u32(Bs[0]), smem_u32(Bs[1]) };
    const __nv_bfloat16* Ag = A + (size_t)rowB * lda;
    const __nv_bfloat16* Bg = B + (size_t)colB * ldb;

    float acc[2][8][4];
#pragma unroll
    for (int i = 0; i < 2; i++)
#pragma unroll
        for (int j = 0; j < 8; j++)
#pragma unroll
            for (int k = 0; k < 4; k++) acc[i][j][k] = 0.f;

    const int NCH = K >> 5;
    cp_chunk<128>(as[0], Ag, lda, tid);
    cp_chunk<128>(bs[0], Bg, ldb, tid);
    CP_COMMIT;
    for (int kc = 0; kc < NCH; kc++) {
        if (kc + 1 < NCH) {
            int nb = (kc + 1) & 1;
            cp_chunk<128>(as[nb], Ag + (kc + 1) * 32, lda, tid);
            cp_chunk<128>(bs[nb], Bg + (kc + 1) * 32, ldb, tid);
            CP_COMMIT;
            CP_WAIT1;
        } else {
            CP_WAIT0;
        }
        __syncthreads();
        mma_chunk<8>(acc, as[kc & 1], bs[kc & 1], wm, wn, lane);
        __syncthreads();
    }

#pragma unroll
    for (int mt = 0; mt < 2; mt++) {
#pragma unroll
        for (int nt = 0; nt < 8; nt++) {
            const float* ac = acc[mt][nt];
            const int r0 = rowB + wm * 32 + mt * 16 + (lane >> 2);
            const int c = colB + wn * 64 + nt * 8 + (lane & 3) * 2;
            const float b0 = bias[c], b1 = bias[c + 1];
            if (EPI == 2) {
                float* C = (float*)Cout;
                float2 ra = *(const float2*)(res + (size_t)r0 * ldc + c);
                float2 rb = *(const float2*)(res + (size_t)(r0 + 8) * ldc + c);
                float2 o0 = { ac[0] + b0 + ra.x, ac[1] + b1 + ra.y };
                float2 o1 = { ac[2] + b0 + rb.x, ac[3] + b1 + rb.y };
                *(float2*)(C + (size_t)r0 * ldc + c) = o0;
                *(float2*)(C + (size_t)(r0 + 8) * ldc + c) = o1;
            } else {
                __nv_bfloat16* C = (__nv_bfloat16*)Cout;
                float v0 = ac[0] + b0, v1 = ac[1] + b1;
                float v2 = ac[2] + b0, v3 = ac[3] + b1;
                if (EPI == 1) { v0 = gelu_f(v0); v1 = gelu_f(v1); v2 = gelu_f(v2); v3 = gelu_f(v3); }
                *(uint32_t*)(C + (size_t)r0 * ldc + c) = pack_bf2(v0, v1);
                *(uint32_t*)(C + (size_t)(r0 + 8) * ldc + c) = pack_bf2(v2, v3);
            }
        }
    }
}

// ---------------- scores: S = Q K^T / 8 + alibi, causal (lower-tri tiles only) -------
__global__ __launch_bounds__(256, 2)
void mm_scores(const __nv_bfloat16* __restrict__ qkv, const float* __restrict__ alibi,
               float* __restrict__ scores)
{
    const int rowT = blockIdx.y, colT = blockIdx.x;
    if (colT > rowT) return;
    __shared__ __nv_bfloat16 As[2][128 * KPAD];
    __shared__ __nv_bfloat16 Bs[2][128 * KPAD];
    const int tid = threadIdx.x, wid = tid >> 5, lane = tid & 31;
    const int wm = wid & 3, wn = wid >> 2;
    const int z = blockIdx.z, b = z >> 4, h = z & 15;
    const uint32_t as[2] = { smem_u32(As[0]), smem_u32(As[1]) };
    const uint32_t bs[2] = { smem_u32(Bs[0]), smem_u32(Bs[1]) };

    const __nv_bfloat16* Q  = qkv + ((size_t)(b * SEQ) + rowT * 128) * QKVDIM + h * DHEAD;
    const __nv_bfloat16* Kp = qkv + ((size_t)(b * SEQ) + colT * 128) * QKVDIM + HID + h * DHEAD;

    float acc[2][8][4];
#pragma unroll
    for (int i = 0; i < 2; i++)
#pragma unroll
        for (int j = 0; j < 8; j++)
#pragma unroll
            for (int k = 0; k < 4; k++) acc[i][j][k] = 0.f;

    cp_chunk<128>(as[0], Q, QKVDIM, tid);
    cp_chunk<128>(bs[0], Kp, QKVDIM, tid);
    CP_COMMIT;
    cp_chunk<128>(as[1], Q + 32, QKVDIM, tid);
    cp_chunk<128>(bs[1], Kp + 32, QKVDIM, tid);
    CP_COMMIT;
    CP_WAIT1;
    __syncthreads();
    mma_chunk<8>(acc, as[0], bs[0], wm, wn, lane);
    CP_WAIT0;
    __syncthreads();
    mma_chunk<8>(acc, as[1], bs[1], wm, wn, lane);

    const float* al = alibi + (size_t)z * SEQ;
    float* C = scores + (size_t)z * SEQ * SEQ;
#pragma unroll
    for (int mt = 0; mt < 2; mt++) {
#pragma unroll
        for (int nt = 0; nt < 8; nt++) {
            const float* ac = acc[mt][nt];
            const int r0 = rowT * 128 + wm * 32 + mt * 16 + (lane >> 2);
            const int c = colT * 128 + wn * 64 + nt * 8 + (lane & 3) * 2;
            const float a0 = al[c], a1 = al[c + 1];
            float2 o0, o1;
            o0.x = (c     <= r0    ) ? ac[0] * 0.125f + a0 : -10000.0f;
            o0.y = (c + 1 <= r0    ) ? ac[1] * 0.125f + a1 : -10000.0f;
            o1.x = (c     <= r0 + 8) ? ac[2] * 0.125f + a0 : -10000.0f;
            o1.y = (c + 1 <= r0 + 8) ? ac[3] * 0.125f + a1 : -10000.0f;
            *(float2*)(C + (size_t)r0 * SEQ + c) = o0;
            *(float2*)(C + (size_t)(r0 + 8) * SEQ + c) = o1;
        }
    }
}

// ---------------- PV: ctx[q,d] = sum_k P[q,k] Vt[d,k], causal-truncated K -----------
__global__ __launch_bounds__(256, 2)
void mm_pv(const __nv_bfloat16* __restrict__ probs, const __nv_bfloat16* __restrict__ vt,
           __nv_bfloat16* __restrict__ ctx)
{
    __shared__ __nv_bfloat16 As[2][128 * KPAD];
    __shared__ __nv_bfloat16 Bs[2][64 * KPAD];
    const int tid = threadIdx.x, wid = tid >> 5, lane = tid & 31;
    const int wm = wid & 3, wn = wid >> 2;
    const int qt = blockIdx.x, z = blockIdx.z, b = z >> 4, h = z & 15;
    const uint32_t as[2] = { smem_u32(As[0]), smem_u32(As[1]) };
    const uint32_t bs[2] = { smem_u32(Bs[0]), smem_u32(Bs[1]) };

    const __nv_bfloat16* Ag = probs + (size_t)z * SEQ * SEQ + (size_t)qt * 128 * SEQ;
    const __nv_bfloat16* Bg = vt + (size_t)z * DHEAD * SEQ;

    float acc[2][4][4];
#pragma unroll
    for (int i = 0; i < 2; i++)
#pragma unroll
        for (int j = 0; j < 4; j++)
#pragma unroll
            for (int k = 0; k < 4; k++) acc[i][j][k] = 0.f;

    const int NCH = (qt + 1) * 4;
    cp_chunk<128>(as[0], Ag, SEQ, tid);
    cp_chunk<64>(bs[0], Bg, SEQ, tid);
    CP_COMMIT;
    for (int kc = 0; kc < NCH; kc++) {
        if (kc + 1 < NCH) {
            int nb = (kc + 1) & 1;
            cp_chunk<128>(as[nb], Ag + (kc + 1) * 32, SEQ, tid);
            cp_chunk<64>(bs[nb], Bg + (kc + 1) * 32, SEQ, tid);
            CP_COMMIT;
            CP_WAIT1;
        } else {
            CP_WAIT0;
        }
        __syncthreads();
        mma_chunk<4>(acc, as[kc & 1], bs[kc & 1], wm, wn, lane);
        __syncthreads();
    }

#pragma unroll
    for (int mt = 0; mt < 2; mt++) {
#pragma unroll
        for (int nt = 0; nt < 4; nt++) {
            const float* ac = acc[mt][nt];
            const int r_in = wm * 32 + mt * 16 + (lane >> 2);
            const int token = b * SEQ + qt * 128 + r_in;
            const int c = h * DHEAD + wn * 32 + nt * 8 + (lane & 3) * 2;
            *(uint32_t*)(ctx + (size_t)token * HID + c) = pack_bf2(ac[0], ac[1]);
            *(uint32_t*)(ctx + (size_t)(token + 8) * HID + c) = pack_bf2(ac[2], ac[3]);
        }
    }
}

// ---------------- launch ----------------
extern "C" void kernel_launch(void* const* d_in, const int* in_sizes, int n_in,
                              void* d_out, int out_size)
{
    (void)in_sizes; (void)n_in; (void)out_size;
    const float* hidden  = (const float*)d_in[0];
    const float* alibi   = (const float*)d_in[1];
    const float* qkv_w   = (const float*)d_in[2];
    const float* qkv_b   = (const float*)d_in[3];
    const float* dense_w = (const float*)d_in[4];
    const float* dense_b = (const float*)d_in[5];
    const float* w1      = (const float*)d_in[6];
    const float* b1      = (const float*)d_in[7];
    const float* w2      = (const float*)d_in[8];
    const float* b2      = (const float*)d_in[9];
    const float* ln1w    = (const float*)d_in[10];
    const float* ln1b    = (const float*)d_in[11];
    const float* ln2w    = (const float*)d_in[12];
    const float* ln2b    = (const float*)d_in[13];
    float* x = (float*)d_out;

    __nv_bfloat16 *ph, *pqkv, *pprobs, *pvt, *pctx, *pff, *pwq, *pwd, *pw1, *pw2;
    float* pscores;
    cudaGetSymbolAddress((void**)&ph,      g_h);
    cudaGetSymbolAddress((void**)&pqkv,    g_qkv);
    cudaGetSymbolAddress((void**)&pscores, g_scores);
    cudaGetSymbolAddress((void**)&pprobs,  g_probs);
    cudaGetSymbolAddress((void**)&pvt,     g_vt);
    cudaGetSymbolAddress((void**)&pctx,    g_ctx);
    cudaGetSymbolAddress((void**)&pff,     g_ff);
    cudaGetSymbolAddress((void**)&pwq,     g_wq);
    cudaGetSymbolAddress((void**)&pwd,     g_wd);
    cudaGetSymbolAddress((void**)&pw1,     g_w1);
    cudaGetSymbolAddress((void**)&pw2,     g_w2);

    cudaMemcpyAsync(x, hidden, sizeof(float) * (size_t)NTOK * HID, cudaMemcpyDeviceToDevice);

    // weights -> bf16 (all layers at once)
    cvt_kernel<<<(NLAYER * QKVDIM * HID / 4 + 255) / 256, 256>>>(qkv_w, pwq, NLAYER * QKVDIM * HID / 4);
    cvt_kernel<<<(NLAYER * HID * HID / 4 + 255) / 256, 256>>>(dense_w, pwd, NLAYER * HID * HID / 4);
    cvt_kernel<<<(NLAYER * FFDIM * HID / 4 + 255) / 256, 256>>>(w1, pw1, NLAYER * FFDIM * HID / 4);
    cvt_kernel<<<(NLAYER * HID * FFDIM / 4 + 255) / 256, 256>>>(w2, pw2, NLAYER * HID * FFDIM / 4);

    for (int l = 0; l < NLAYER; l++) {
        // --- attention ---
        ln_kernel<<<NTOK, 256>>>(x, ln1w + l * HID, ln1b + l * HID, ph);
        mm_gemm<0><<<dim3(QKVDIM / 128, NTOK / 128), 256>>>(
            ph, HID, pwq + (size_t)l * QKVDIM * HID, HID,
            qkv_b + (size_t)l * QKVDIM, nullptr, pqkv, QKVDIM, HID);
        vtrans_kernel<<<dim3(SEQ / 32, DHEAD / 32, BATCH * NHEAD), dim3(32, 32)>>>(pqkv, pvt);
        mm_scores<<<dim3(SEQ / 128, SEQ / 128, BATCH * NHEAD), 256>>>(pqkv, alibi, pscores);
        softmax_kernel<<<BATCH * NHEAD * SEQ, 256>>>(pscores, pprobs);
        mm_pv<<<dim3(SEQ / 128, 1, BATCH * NHEAD), 256>>>(pprobs, pvt, pctx);
        mm_gemm<2><<<dim3(HID / 128, NTOK / 128), 256>>>(
            pctx, HID, pwd + (size_t)l * HID * HID, HID,
            dense_b + (size_t)l * HID, x, x, HID, HID);
        // --- MLP ---
        ln_kernel<<<NTOK, 256>>>(x, ln2w + l * HID, ln2b + l * HID, ph);
        mm_gemm<1><<<dim3(FFDIM / 128, NTOK / 128), 256>>>(
            ph, HID, pw1 + (size_t)l * FFDIM * HID, HID,
            b1 + (size_t)l * FFDIM, nullptr, pff, FFDIM, HID);
        mm_gemm<2><<<dim3(HID / 128, NTOK / 128), 256>>>(
            pff, FFDIM, pw2 + (size_t)l * HID * FFDIM, FFDIM,
            b2 + (size_t)l * HID, x, x, HID, FFDIM);
    }
}

// round 5
// speedup vs baseline: 7.5516x; 1.3361x over previous
#include <cuda_runtime.h>
#include <cuda_bf16.h>
#include <math.h>
#include <stdint.h>

#define NLAYER 2
#define BATCH  2
#define SEQ    2048
#define HID    1024
#define NHEAD  16
#define DHEAD  64
#define FFDIM  4096
#define NTOK   (BATCH*SEQ)      // 4096
#define QKVDIM (3*HID)          // 3072
#define KPAD   40               // GEMM: 32-elem K chunk padded to 40
#define KPQ    72               // flash: 64-elem rows padded to 72
#define KPV    136              // flash: 128-elem rows padded to 136

// ---------------- scratch (device globals) ----------------
__device__ __nv_bfloat16 g_h[NTOK*HID];
__device__ __nv_bfloat16 g_qkv[(size_t)NTOK*QKVDIM];
__device__ __nv_bfloat16 g_vt[(size_t)BATCH*NHEAD*DHEAD*SEQ];
__device__ __nv_bfloat16 g_ctx[NTOK*HID];
__device__ __nv_bfloat16 g_ff[(size_t)NTOK*FFDIM];
__device__ __nv_bfloat16 g_wq[(size_t)NLAYER*QKVDIM*HID];
__device__ __nv_bfloat16 g_wd[(size_t)NLAYER*HID*HID];
__device__ __nv_bfloat16 g_w1[(size_t)NLAYER*FFDIM*HID];
__device__ __nv_bfloat16 g_w2[(size_t)NLAYER*HID*FFDIM];

// ---------------- helpers ----------------
__device__ __forceinline__ uint32_t smem_u32(const void* p) {
    uint32_t a;
    asm("{ .reg .u64 t; cvta.to.shared.u64 t, %1; cvt.u32.u64 %0, t; }" : "=r"(a) : "l"(p));
    return a;
}
__device__ __forceinline__ void cp16(uint32_t s, const void* g) {
    asm volatile("cp.async.cg.shared.global [%0], [%1], 16;" :: "r"(s), "l"(g));
}
#define CP_COMMIT asm volatile("cp.async.commit_group;")
#define CP_WAIT1  asm volatile("cp.async.wait_group 1;")
#define CP_WAIT0  asm volatile("cp.async.wait_group 0;")

__device__ __forceinline__ void ldmx4(uint32_t* r, uint32_t addr) {
    asm volatile("ldmatrix.sync.aligned.m8n8.x4.shared.b16 {%0,%1,%2,%3}, [%4];"
                 : "=r"(r[0]), "=r"(r[1]), "=r"(r[2]), "=r"(r[3]) : "r"(addr));
}
__device__ __forceinline__ void mma16816(float* c, const uint32_t* a, const uint32_t* b) {
    asm volatile("mma.sync.aligned.m16n8k16.row.col.f32.bf16.bf16.f32 "
                 "{%0,%1,%2,%3}, {%4,%5,%6,%7}, {%8,%9}, {%0,%1,%2,%3};"
                 : "+f"(c[0]), "+f"(c[1]), "+f"(c[2]), "+f"(c[3])
                 : "r"(a[0]), "r"(a[1]), "r"(a[2]), "r"(a[3]), "r"(b[0]), "r"(b[1]));
}
__device__ __forceinline__ uint32_t pack_bf2(float a, float b) {
    __nv_bfloat162 h = __floats2bfloat162_rn(a, b);
    return *(uint32_t*)&h;
}
__device__ __forceinline__ float gelu_f(float v) {
    return 0.5f * v * (1.0f + erff(v * 0.70710678118654752440f));
}
__device__ __forceinline__ float warpSum(float v) {
#pragma unroll
    for (int o = 16; o > 0; o >>= 1) v += __shfl_xor_sync(0xffffffffu, v, o);
    return v;
}

// load 128 x 32 bf16 chunk from g (row stride ld elems) into smem (KPAD-elem rows)
__device__ __forceinline__ void cp_chunk(uint32_t sbase, const __nv_bfloat16* g, int ld, int tid) {
#pragma unroll
    for (int it = 0; it < 2; it++) {
        int idx = tid + it * 256;
        int row = idx >> 2, q = idx & 3;
        cp16(sbase + (uint32_t)(row * KPAD + q * 8) * 2, g + (size_t)row * ld + q * 8);
    }
}

// one 32-wide K-chunk of warp-level MMAs (128x128 CTA tile, 4x2 warps, 32x64 warp tile)
__device__ __forceinline__ void mma_chunk(float (&acc)[2][8][4], uint32_t abase, uint32_t bbase,
                                          int wm, int wn, int lane) {
#pragma unroll
    for (int ks = 0; ks < 32; ks += 16) {
        uint32_t a[2][4];
#pragma unroll
        for (int mt = 0; mt < 2; mt++) {
            int row = wm * 32 + mt * 16 + (lane & 7) + ((lane >> 3) & 1) * 8;
            int col = ks + ((lane >> 4) & 1) * 8;
            ldmx4(a[mt], abase + (uint32_t)(row * KPAD + col) * 2);
        }
        uint32_t bf[8][2];
#pragma unroll
        for (int nb = 0; nb < 4; nb++) {
            int row = wn * 64 + nb * 16 + (lane & 7) + ((lane >> 4) & 1) * 8;
            int col = ks + ((lane >> 3) & 1) * 8;
            uint32_t r[4];
            ldmx4(r, bbase + (uint32_t)(row * KPAD + col) * 2);
            bf[2 * nb][0] = r[0]; bf[2 * nb][1] = r[1];
            bf[2 * nb + 1][0] = r[2]; bf[2 * nb + 1][1] = r[3];
        }
#pragma unroll
        for (int mt = 0; mt < 2; mt++)
#pragma unroll
            for (int nt = 0; nt < 8; nt++)
                mma16816(acc[mt][nt], a[mt], bf[nt]);
    }
}

// ---------------- LayerNorm (fp32 in, bf16 out) ----------------
__global__ __launch_bounds__(256)
void ln_kernel(const float* __restrict__ x, const float* __restrict__ w,
               const float* __restrict__ b, __nv_bfloat16* __restrict__ out)
{
    __shared__ float sh[8];
    __shared__ float stat;
    const int t = blockIdx.x;
    const float* xr = x + (size_t)t * HID;
    const int lane = threadIdx.x & 31, wp = threadIdx.x >> 5;

    float v[4];
    float s = 0.f;
#pragma unroll
    for (int i = 0; i < 4; i++) { v[i] = xr[threadIdx.x + i * 256]; s += v[i]; }
    s = warpSum(s);
    if (lane == 0) sh[wp] = s;
    __syncthreads();
    if (threadIdx.x == 0) {
        float r = 0.f;
#pragma unroll
        for (int i = 0; i < 8; i++) r += sh[i];
        stat = r * (1.0f / HID);
    }
    __syncthreads();
    const float mu = stat;

    float s2 = 0.f;
#pragma unroll
    for (int i = 0; i < 4; i++) { float d = v[i] - mu; s2 += d * d; }
    s2 = warpSum(s2);
    __syncthreads();
    if (lane == 0) sh[wp] = s2;
    __syncthreads();
    if (threadIdx.x == 0) {
        float r = 0.f;
#pragma unroll
        for (int i = 0; i < 8; i++) r += sh[i];
        stat = rsqrtf(r * (1.0f / HID) + 1e-5f);
    }
    __syncthreads();
    const float rs = stat;

    __nv_bfloat16* orow = out + (size_t)t * HID;
#pragma unroll
    for (int i = 0; i < 4; i++) {
        int c = threadIdx.x + i * 256;
        orow[c] = __float2bfloat16((v[i] - mu) * rs * w[c] + b[c]);
    }
}

// ---------------- weight convert fp32 -> bf16 ----------------
__global__ __launch_bounds__(256)
void cvt_kernel(const float* __restrict__ src, __nv_bfloat16* __restrict__ dst, int n4)
{
    int i = blockIdx.x * 256 + threadIdx.x;
    if (i < n4) {
        float4 v = ((const float4*)src)[i];
        uint2 o;
        o.x = pack_bf2(v.x, v.y);
        o.y = pack_bf2(v.z, v.w);
        ((uint2*)dst)[i] = o;
    }
}

// ---------------- V transpose: qkv v-part -> [B,NH,DH,S] ----------------
__global__ void vtrans_kernel(const __nv_bfloat16* __restrict__ qkv, __nv_bfloat16* __restrict__ vt)
{
    __shared__ __nv_bfloat16 t[32][33];
    const int z = blockIdx.z, b = z >> 4, h = z & 15;
    const int s0 = blockIdx.x * 32, d0 = blockIdx.y * 32;
    const int tx = threadIdx.x, ty = threadIdx.y;
    t[ty][tx] = qkv[(size_t)(b * SEQ + s0 + ty) * QKVDIM + 2 * HID + h * DHEAD + d0 + tx];
    __syncthreads();
    vt[(size_t)z * DHEAD * SEQ + (size_t)(d0 + ty) * SEQ + s0 + tx] = t[tx][ty];
}

// ---------------- flash attention: ctx = softmax(QK^T/8 + alibi, causal) V ----------
// grid (16 qtiles [reversed], B*NH). 8 warps, each owns 16 q-rows x full 128 k-tile.
__global__ __launch_bounds__(256)
void flash_kernel(const __nv_bfloat16* __restrict__ qkv,
                  const __nv_bfloat16* __restrict__ vt,
                  const float* __restrict__ alibi,
                  __nv_bfloat16* __restrict__ ctx)
{
    extern __shared__ __nv_bfloat16 sm[];
    const int tid = threadIdx.x, wid = tid >> 5, lane = tid & 31;
    const int qt = (int)gridDim.x - 1 - (int)blockIdx.x;   // big tiles first
    const int z = blockIdx.y, b = z >> 4, h = z & 15;

    const uint32_t qsa = smem_u32(sm);                              // Q: 128 x KPQ
    const uint32_t ksa[2] = { qsa + 128 * KPQ * 2, qsa + 2 * 128 * KPQ * 2 };
    const uint32_t vsa[2] = { qsa + 3 * 128 * KPQ * 2, qsa + 3 * 128 * KPQ * 2 + 64 * KPV * 2 };

    const __nv_bfloat16* Qg = qkv + ((size_t)(b * SEQ) + qt * 128) * QKVDIM + h * DHEAD;
    const __nv_bfloat16* Kg = qkv + (size_t)(b * SEQ) * QKVDIM + HID + h * DHEAD;
    const __nv_bfloat16* Vg = vt + (size_t)z * DHEAD * SEQ;
    const float slope = alibi[(size_t)z * SEQ + 1];   // alibi[...,c] == slope*c exactly

    // tile loaders: Q/K = 128 rows x 64 elems; V = 64 rows x 128 elems
    {
#pragma unroll
        for (int it = 0; it < 4; it++) {
            int idx = tid + it * 256, row = idx >> 3, u = idx & 7;
            cp16(qsa + (uint32_t)(row * KPQ + u * 8) * 2, Qg + (size_t)row * QKVDIM + u * 8);
        }
#pragma unroll
        for (int it = 0; it < 4; it++) {
            int idx = tid + it * 256, row = idx >> 3, u = idx & 7;
            cp16(ksa[0] + (uint32_t)(row * KPQ + u * 8) * 2, Kg + (size_t)row * QKVDIM + u * 8);
        }
#pragma unroll
        for (int it = 0; it < 4; it++) {
            int idx = tid + it * 256, row = idx >> 4, u = idx & 15;
            cp16(vsa[0] + (uint32_t)(row * KPV + u * 8) * 2, Vg + (size_t)row * SEQ + u * 8);
        }
        CP_COMMIT;
    }
    CP_WAIT0;
    __syncthreads();

    // Q fragments: warp rows wid*16..+15, 4 k16-chunks over DH=64
    uint32_t aQ[4][4];
#pragma unroll
    for (int kc = 0; kc < 4; kc++) {
        int row = wid * 16 + (lane & 7) + ((lane >> 3) & 1) * 8;
        int col = kc * 16 + ((lane >> 4) & 1) * 8;
        ldmx4(aQ[kc], qsa + (uint32_t)(row * KPQ + col) * 2);
    }

    float m0 = -1e30f, m1 = -1e30f, l0 = 0.f, l1 = 0.f;
    float oacc[8][4];
#pragma unroll
    for (int i = 0; i < 8; i++)
#pragma unroll
        for (int j = 0; j < 4; j++) oacc[i][j] = 0.f;

    const int rg0 = qt * 128 + wid * 16 + (lane >> 2);
    const int rg1 = rg0 + 8;

    for (int kt = 0; kt <= qt; kt++) {
        const int cur = kt & 1;
        if (kt < qt) {   // prefetch next K/V into other buffer (freed by sync at prev iter end)
            const __nv_bfloat16* Kn = Kg + (size_t)(kt + 1) * 128 * QKVDIM;
            const __nv_bfloat16* Vn = Vg + (kt + 1) * 128;
#pragma unroll
            for (int it = 0; it < 4; it++) {
                int idx = tid + it * 256, row = idx >> 3, u = idx & 7;
                cp16(ksa[cur ^ 1] + (uint32_t)(row * KPQ + u * 8) * 2, Kn + (size_t)row * QKVDIM + u * 8);
            }
#pragma unroll
            for (int it = 0; it < 4; it++) {
                int idx = tid + it * 256, row = idx >> 4, u = idx & 15;
                cp16(vsa[cur ^ 1] + (uint32_t)(row * KPV + u * 8) * 2, Vn + (size_t)row * SEQ + u * 8);
            }
            CP_COMMIT;
        }

        // S = Q K^T  (16 q-rows x 128 k-cols per warp)
        float sacc[16][4];
#pragma unroll
        for (int i = 0; i < 16; i++)
#pragma unroll
            for (int j = 0; j < 4; j++) sacc[i][j] = 0.f;
#pragma unroll
        for (int kc = 0; kc < 4; kc++) {
#pragma unroll
            for (int nb = 0; nb < 8; nb++) {
                uint32_t r[4];
                int row = nb * 16 + (lane & 7) + ((lane >> 4) & 1) * 8;
                int col = kc * 16 + ((lane >> 3) & 1) * 8;
                ldmx4(r, ksa[cur] + (uint32_t)(row * KPQ + col) * 2);
                mma16816(sacc[2 * nb], aQ[kc], r);
                mma16816(sacc[2 * nb + 1], aQ[kc], r + 2);
            }
        }

        // scale + alibi + causal mask + row max
        float mx0 = -1e30f, mx1 = -1e30f;
        const int cb = kt * 128 + (lane & 3) * 2;
#pragma unroll
        for (int nt = 0; nt < 16; nt++) {
            int c0 = cb + nt * 8, c1 = c0 + 1;
            float a0 = slope * (float)c0, a1 = slope * (float)c1;
            float s0 = (c0 <= rg0) ? fmaf(sacc[nt][0], 0.125f, a0) : -1e30f;
            float s1 = (c1 <= rg0) ? fmaf(sacc[nt][1], 0.125f, a1) : -1e30f;
            float s2 = (c0 <= rg1) ? fmaf(sacc[nt][2], 0.125f, a0) : -1e30f;
            float s3 = (c1 <= rg1) ? fmaf(sacc[nt][3], 0.125f, a1) : -1e30f;
            sacc[nt][0] = s0; sacc[nt][1] = s1; sacc[nt][2] = s2; sacc[nt][3] = s3;
            mx0 = fmaxf(mx0, fmaxf(s0, s1)); mx1 = fmaxf(mx1, fmaxf(s2, s3));
        }
        mx0 = fmaxf(mx0, __shfl_xor_sync(0xffffffffu, mx0, 1));
        mx0 = fmaxf(mx0, __shfl_xor_sync(0xffffffffu, mx0, 2));
        mx1 = fmaxf(mx1, __shfl_xor_sync(0xffffffffu, mx1, 1));
        mx1 = fmaxf(mx1, __shfl_xor_sync(0xffffffffu, mx1, 2));

        const float mn0 = fmaxf(m0, mx0), mn1 = fmaxf(m1, mx1);
        const float sc0 = __expf(m0 - mn0), sc1 = __expf(m1 - mn1);
        float rs0 = 0.f, rs1 = 0.f;
#pragma unroll
        for (int nt = 0; nt < 16; nt++) {
            float p0 = __expf(sacc[nt][0] - mn0), p1 = __expf(sacc[nt][1] - mn0);
            float p2 = __expf(sacc[nt][2] - mn1), p3 = __expf(sacc[nt][3] - mn1);
            sacc[nt][0] = p0; sacc[nt][1] = p1; sacc[nt][2] = p2; sacc[nt][3] = p3;
            rs0 += p0 + p1; rs1 += p2 + p3;
        }
        rs0 += __shfl_xor_sync(0xffffffffu, rs0, 1);
        rs0 += __shfl_xor_sync(0xffffffffu, rs0, 2);
        rs1 += __shfl_xor_sync(0xffffffffu, rs1, 1);
        rs1 += __shfl_xor_sync(0xffffffffu, rs1, 2);
        l0 = l0 * sc0 + rs0; l1 = l1 * sc1 + rs1;
        m0 = mn0; m1 = mn1;
#pragma unroll
        for (int nt = 0; nt < 8; nt++) {
            oacc[nt][0] *= sc0; oacc[nt][1] *= sc0;
            oacc[nt][2] *= sc1; oacc[nt][3] *= sc1;
        }

        // O += P V  (P fragments come straight from sacc registers)
#pragma unroll
        for (int kc2 = 0; kc2 < 8; kc2++) {
            uint32_t pa[4] = {
                pack_bf2(sacc[2 * kc2][0],     sacc[2 * kc2][1]),
                pack_bf2(sacc[2 * kc2][2],     sacc[2 * kc2][3]),
                pack_bf2(sacc[2 * kc2 + 1][0], sacc[2 * kc2 + 1][1]),
                pack_bf2(sacc[2 * kc2 + 1][2], sacc[2 * kc2 + 1][3]) };
#pragma unroll
            for (int nb = 0; nb < 4; nb++) {
                uint32_t r[4];
                int row = nb * 16 + (lane & 7) + ((lane >> 4) & 1) * 8;
                int col = kc2 * 16 + ((lane >> 3) & 1) * 8;
                ldmx4(r, vsa[cur] + (uint32_t)(row * KPV + col) * 2);
                mma16816(oacc[2 * nb], pa, r);
                mma16816(oacc[2 * nb + 1], pa, r + 2);
            }
        }

        if (kt < qt) CP_WAIT0;
        __syncthreads();          // everyone done with buf[cur]; next iter may overwrite
    }

    const float inv0 = 1.0f / l0, inv1 = 1.0f / l1;
    const int tok0 = b * SEQ + qt * 128 + wid * 16 + (lane >> 2);
#pragma unroll
    for (int nt = 0; nt < 8; nt++) {
        int c = h * DHEAD + nt * 8 + (lane & 3) * 2;
        *(uint32_t*)(ctx + (size_t)tok0 * HID + c) = pack_bf2(oacc[nt][0] * inv0, oacc[nt][1] * inv0);
        *(uint32_t*)(ctx + (size_t)(tok0 + 8) * HID + c) = pack_bf2(oacc[nt][2] * inv1, oacc[nt][3] * inv1);
    }
}

// ---------------- bf16 tensor-core NT GEMM, 3-stage pipeline ------------------------
// EPI: 0 = bias -> bf16, 1 = bias+gelu -> bf16, 2 = bias+residual -> fp32
#define STG_B (128 * KPAD * 2)   // bytes per stage per operand
template<int EPI>
__global__ __launch_bounds__(256, 2)
void mm_gemm(const __nv_bfloat16* __restrict__ A, int lda,
             const __nv_bfloat16* __restrict__ B, int ldb,
             const float* __restrict__ bias, const float* __restrict__ res,
             void* __restrict__ Cout, int ldc, int K)
{
    extern __shared__ __nv_bfloat16 smbuf[];
    const uint32_t as0 = smem_u32(smbuf);
    const uint32_t bs0 = as0 + 3 * STG_B;
    const int tid = threadIdx.x, wid = tid >> 5, lane = tid & 31;
    const int wm = wid & 3, wn = wid >> 2;
    const int rowB = blockIdx.y * 128, colB = blockIdx.x * 128;
    const __nv_bfloat16* Ag = A + (size_t)rowB * lda;
    const __nv_bfloat16* Bg = B + (size_t)colB * ldb;

    float acc[2][8][4];
#pragma unroll
    for (int i = 0; i < 2; i++)
#pragma unroll
        for (int j = 0; j < 8; j++)
#pragma unroll
            for (int k = 0; k < 4; k++) acc[i][j][k] = 0.f;

    const int NCH = K >> 5;
    cp_chunk(as0, Ag, lda, tid); cp_chunk(bs0, Bg, ldb, tid); CP_COMMIT;
    cp_chunk(as0 + STG_B, Ag + 32, lda, tid); cp_chunk(bs0 + STG_B, Bg + 32, ldb, tid); CP_COMMIT;

    for (int kc = 0; kc < NCH; kc++) {
        if (kc == NCH - 1) { CP_WAIT0; } else { CP_WAIT1; }
        __syncthreads();
        if (kc + 2 < NCH) {
            int st = (kc + 2) % 3;
            cp_chunk(as0 + st * STG_B, Ag + (kc + 2) * 32, lda, tid);
            cp_chunk(bs0 + st * STG_B, Bg + (kc + 2) * 32, ldb, tid);
            CP_COMMIT;
        }
        int st = kc % 3;
        mma_chunk(acc, as0 + st * STG_B, bs0 + st * STG_B, wm, wn, lane);
    }

#pragma unroll
    for (int mt = 0; mt < 2; mt++) {
#pragma unroll
        for (int nt = 0; nt < 8; nt++) {
            const float* ac = acc[mt][nt];
            const int r0 = rowB + wm * 32 + mt * 16 + (lane >> 2);
            const int c = colB + wn * 64 + nt * 8 + (lane & 3) * 2;
            const float b0 = bias[c], b1 = bias[c + 1];
            if (EPI == 2) {
                float* C = (float*)Cout;
                float2 ra = *(const float2*)(res + (size_t)r0 * ldc + c);
                float2 rb = *(const float2*)(res + (size_t)(r0 + 8) * ldc + c);
                float2 o0 = { ac[0] + b0 + ra.x, ac[1] + b1 + ra.y };
                float2 o1 = { ac[2] + b0 + rb.x, ac[3] + b1 + rb.y };
                *(float2*)(C + (size_t)r0 * ldc + c) = o0;
                *(float2*)(C + (size_t)(r0 + 8) * ldc + c) = o1;
            } else {
                __nv_bfloat16* C = (__nv_bfloat16*)Cout;
                float v0 = ac[0] + b0, v1 = ac[1] + b1;
                float v2 = ac[2] + b0, v3 = ac[3] + b1;
                if (EPI == 1) { v0 = gelu_f(v0); v1 = gelu_f(v1); v2 = gelu_f(v2); v3 = gelu_f(v3); }
                *(uint32_t*)(C + (size_t)r0 * ldc + c) = pack_bf2(v0, v1);
                *(uint32_t*)(C + (size_t)(r0 + 8) * ldc + c) = pack_bf2(v2, v3);
            }
        }
    }
}

// ---------------- launch ----------------
extern "C" void kernel_launch(void* const* d_in, const int* in_sizes, int n_in,
                              void* d_out, int out_size)
{
    (void)in_sizes; (void)n_in; (void)out_size;
    const float* hidden  = (const float*)d_in[0];
    const float* alibi   = (const float*)d_in[1];
    const float* qkv_w   = (const float*)d_in[2];
    const float* qkv_b   = (const float*)d_in[3];
    const float* dense_w = (const float*)d_in[4];
    const float* dense_b = (const float*)d_in[5];
    const float* w1      = (const float*)d_in[6];
    const float* b1      = (const float*)d_in[7];
    const float* w2      = (const float*)d_in[8];
    const float* b2      = (const float*)d_in[9];
    const float* ln1w    = (const float*)d_in[10];
    const float* ln1b    = (const float*)d_in[11];
    const float* ln2w    = (const float*)d_in[12];
    const float* ln2b    = (const float*)d_in[13];
    float* x = (float*)d_out;

    __nv_bfloat16 *ph, *pqkv, *pvt, *pctx, *pff, *pwq, *pwd, *pw1, *pw2;
    cudaGetSymbolAddress((void**)&ph,   g_h);
    cudaGetSymbolAddress((void**)&pqkv, g_qkv);
    cudaGetSymbolAddress((void**)&pvt,  g_vt);
    cudaGetSymbolAddress((void**)&pctx, g_ctx);
    cudaGetSymbolAddress((void**)&pff,  g_ff);
    cudaGetSymbolAddress((void**)&pwq,  g_wq);
    cudaGetSymbolAddress((void**)&pwd,  g_wd);
    cudaGetSymbolAddress((void**)&pw1,  g_w1);
    cudaGetSymbolAddress((void**)&pw2,  g_w2);

    const int GEMM_SMEM  = 6 * STG_B;                                  // 61440
    const int FLASH_SMEM = (3 * 128 * KPQ + 2 * 64 * KPV) * 2;         // 90112
    cudaFuncSetAttribute(mm_gemm<0>, cudaFuncAttributeMaxDynamicSharedMemorySize, GEMM_SMEM);
    cudaFuncSetAttribute(mm_gemm<1>, cudaFuncAttributeMaxDynamicSharedMemorySize, GEMM_SMEM);
    cudaFuncSetAttribute(mm_gemm<2>, cudaFuncAttributeMaxDynamicSharedMemorySize, GEMM_SMEM);
    cudaFuncSetAttribute(flash_kernel, cudaFuncAttributeMaxDynamicSharedMemorySize, FLASH_SMEM);

    cudaMemcpyAsync(x, hidden, sizeof(float) * (size_t)NTOK * HID, cudaMemcpyDeviceToDevice);

    // weights -> bf16 (all layers at once)
    cvt_kernel<<<(NLAYER * QKVDIM * HID / 4 + 255) / 256, 256>>>(qkv_w, pwq, NLAYER * QKVDIM * HID / 4);
    cvt_kernel<<<(NLAYER * HID * HID / 4 + 255) / 256, 256>>>(dense_w, pwd, NLAYER * HID * HID / 4);
    cvt_kernel<<<(NLAYER * FFDIM * HID / 4 + 255) / 256, 256>>>(w1, pw1, NLAYER * FFDIM * HID / 4);
    cvt_kernel<<<(NLAYER * HID * FFDIM / 4 + 255) / 256, 256>>>(w2, pw2, NLAYER * HID * FFDIM / 4);

    for (int l = 0; l < NLAYER; l++) {
        // --- attention ---
        ln_kernel<<<NTOK, 256>>>(x, ln1w + l * HID, ln1b + l * HID, ph);
        mm_gemm<0><<<dim3(QKVDIM / 128, NTOK / 128), 256, GEMM_SMEM>>>(
            ph, HID, pwq + (size_t)l * QKVDIM * HID, HID,
            qkv_b + (size_t)l * QKVDIM, nullptr, pqkv, QKVDIM, HID);
        vtrans_kernel<<<dim3(SEQ / 32, DHEAD / 32, BATCH * NHEAD), dim3(32, 32)>>>(pqkv, pvt);
        flash_kernel<<<dim3(SEQ / 128, BATCH * NHEAD), 256, FLASH_SMEM>>>(pqkv, pvt, alibi, pctx);
        mm_gemm<2><<<dim3(HID / 128, NTOK / 128), 256, GEMM_SMEM>>>(
            pctx, HID, pwd + (size_t)l * HID * HID, HID,
            dense_b + (size_t)l * HID, x, x, HID, HID);
        // --- MLP ---
        ln_kernel<<<NTOK, 256>>>(x, ln2w + l * HID, ln2b + l * HID, ph);
        mm_gemm<1><<<dim3(FFDIM / 128, NTOK / 128), 256, GEMM_SMEM>>>(
            ph, HID, pw1 + (size_t)l * FFDIM * HID, HID,
            b1 + (size_t)l * FFDIM, nullptr, pff, FFDIM, HID);
        mm_gemm<2><<<dim3(HID / 128, NTOK / 128), 256, GEMM_SMEM>>>(
            pff, FFDIM, pw2 + (size_t)l * HID * FFDIM, FFDIM,
            b2 + (size_t)l * HID, x, x, HID, FFDIM);
    }
}